// round 3
// baseline (speedup 1.0000x reference)
#include <cuda_runtime.h>

#define MAXN 100000
#define MAXE 1600000

// ---------------- scratch (device globals; no runtime allocation) ----------
__device__ float g_bufA[MAXN * 128];        // 51.2 MB
__device__ float g_bufB[MAXN * 128];        // 51.2 MB
__device__ float g_bufC[MAXN * 128];        // 51.2 MB
__device__ float g_sums[MAXN * 2 * 128];    // 102.4 MB  per-(node,rel) sums
__device__ float g_inv[MAXN * 2];           // counts -> 1/max(cnt,1)
__device__ int   g_flag[1];                 // 1 => indices are int64

__device__ __forceinline__ float* dbuf(int s) {
    return (s == 0) ? g_bufA : (s == 1) ? g_bufB : g_bufC;
}

__device__ __forceinline__ float lrelu(float v) {
    return v > 0.f ? v : 0.01f * v;
}

// ---------------- dtype detection: int64 vs int32 edge indices -------------
// Node ids < 100000 < 2^31, so if data is int64 every odd 32-bit word is 0.
__global__ void detect_kernel(const int* __restrict__ ei) {
    __shared__ int s_nz;
    if (threadIdx.x == 0) s_nz = 0;
    __syncthreads();
    for (int p = threadIdx.x; p < 1024; p += blockDim.x) {
        if (ei[2 * p + 1] != 0) s_nz = 1;
    }
    __syncthreads();
    if (threadIdx.x == 0) g_flag[0] = (s_nz == 0) ? 1 : 0;
}

// ---------------- zero sums (+ optionally counts) ---------------------------
__global__ void zero_kernel(long n4, int zero_inv, int n2) {
    long stride = (long)gridDim.x * blockDim.x;
    long t0 = (long)blockIdx.x * blockDim.x + threadIdx.x;
    float4 z = make_float4(0.f, 0.f, 0.f, 0.f);
    float4* s4 = (float4*)g_sums;
    for (long i = t0; i < n4; i += stride) s4[i] = z;
    if (zero_inv) {
        for (long i = t0; i < n2; i += stride) g_inv[i] = 0.f;
    }
}

// ---------------- feature fusion: 4 small linears + lrelu -> bufA ----------
__global__ void fuse_kernel(const float* __restrict__ des, const float* __restrict__ tw,
                            const float* __restrict__ nprop, const float* __restrict__ cprop,
                            const float* __restrict__ Wd, const float* __restrict__ bd,
                            const float* __restrict__ Wt, const float* __restrict__ bt,
                            const float* __restrict__ Wn, const float* __restrict__ bn,
                            const float* __restrict__ Wc, const float* __restrict__ bc,
                            int n) {
    __shared__ float sW[100 * 32];
    __shared__ float sB[32];
    __shared__ float sIn[64 * 100];
    int tid = threadIdx.x;
    int n0 = blockIdx.x * 64;
    int node = tid >> 2;
    int c0 = (tid & 3) * 8;

    const float* ins[4] = {des, tw, nprop, cprop};
    const float* Ws[4]  = {Wd, Wt, Wn, Wc};
    const float* Bs[4]  = {bd, bt, bn, bc};
    const int    Ks[4]  = {100, 100, 6, 11};

    for (int s = 0; s < 4; s++) {
        int K = Ks[s];
        const float* W = Ws[s];
        for (int i = tid; i < K * 32; i += 256) sW[i] = W[i];
        if (tid < 32) sB[tid] = Bs[s][tid];
        const float* in = ins[s];
        for (int i = tid; i < 64 * K; i += 256) {
            int r = i / K, c = i - r * K;
            int row = n0 + r;
            sIn[i] = (row < n) ? in[(long)row * K + c] : 0.f;
        }
        __syncthreads();

        float acc[8];
        #pragma unroll
        for (int j = 0; j < 8; j++) acc[j] = sB[c0 + j];
        const float4* sW4 = (const float4*)sW;
        int wbase = c0 >> 2;
        for (int k = 0; k < K; k++) {
            float a = sIn[node * K + k];
            float4 w0 = sW4[k * 8 + wbase];
            float4 w1 = sW4[k * 8 + wbase + 1];
            acc[0] += a * w0.x; acc[1] += a * w0.y; acc[2] += a * w0.z; acc[3] += a * w0.w;
            acc[4] += a * w1.x; acc[5] += a * w1.y; acc[6] += a * w1.z; acc[7] += a * w1.w;
        }
        int row = n0 + node;
        if (row < n) {
            float* o = g_bufA + (long)row * 128 + s * 32 + c0;
            #pragma unroll
            for (int j = 0; j < 8; j++) o[j] = lrelu(acc[j]);
        }
        __syncthreads();
    }
}

// ---------------- generic [N,128]@[128,128] + bias (+lrelu) ----------------
__global__ void gemm128_kernel(int selA, int selC, const float* __restrict__ W,
                               const float* __restrict__ bias, int n, int act) {
    extern __shared__ float sm[];
    float* sW = sm;              // 128*128
    float* sA = sm + 16384;      // 64*128
    int tid = threadIdx.x;
    int n0 = blockIdx.x * 64;
    const float* A = dbuf(selA);
    float* C = dbuf(selC);

    float4* sW4 = (float4*)sW;
    const float4* Wg = (const float4*)W;
    for (int i = tid; i < 4096; i += 256) sW4[i] = Wg[i];
    float4* sA4 = (float4*)sA;
    const float4* Ag = (const float4*)A;
    for (int i = tid; i < 2048; i += 256) {
        int r = i >> 5;
        int row = n0 + r;
        sA4[i] = (row < n) ? Ag[(long)row * 32 + (i & 31)] : make_float4(0.f, 0.f, 0.f, 0.f);
    }
    __syncthreads();

    int tx = tid & 31, ty = tid >> 5;
    float acc[8][4];
    #pragma unroll
    for (int i = 0; i < 8; i++) { acc[i][0] = acc[i][1] = acc[i][2] = acc[i][3] = 0.f; }
    const float* a0 = sA + ty * 8 * 128;
    #pragma unroll 4
    for (int k = 0; k < 128; k++) {
        float4 w = sW4[k * 32 + tx];
        #pragma unroll
        for (int i = 0; i < 8; i++) {
            float a = a0[i * 128 + k];
            acc[i][0] += a * w.x; acc[i][1] += a * w.y;
            acc[i][2] += a * w.z; acc[i][3] += a * w.w;
        }
    }
    float4 bv = ((const float4*)bias)[tx];
    #pragma unroll
    for (int i = 0; i < 8; i++) {
        int row = n0 + ty * 8 + i;
        if (row < n) {
            float4 o;
            o.x = acc[i][0] + bv.x; o.y = acc[i][1] + bv.y;
            o.z = acc[i][2] + bv.z; o.w = acc[i][3] + bv.w;
            if (act) { o.x = lrelu(o.x); o.y = lrelu(o.y); o.z = lrelu(o.z); o.w = lrelu(o.w); }
            ((float4*)C)[(long)row * 32 + tx] = o;
        }
    }
}

// ---------------- counts -> 1/max(cnt,1) ------------------------------------
__global__ void inv_kernel(int n2) {
    int i = blockIdx.x * blockDim.x + threadIdx.x;
    if (i < n2) {
        float c = g_inv[i];
        g_inv[i] = 1.0f / fmaxf(c, 1.0f);
    }
}

// ---------------- scatter: warp per edge, float4 vector atomics -------------
// do_count=1: also accumulate per-(dst,rel) edge counts into g_inv (lane 0).
__global__ void scatter_kernel(int selX, const void* __restrict__ ei,
                               const void* __restrict__ et, int E, int do_count) {
    long gt = (long)blockIdx.x * blockDim.x + threadIdx.x;
    long e = gt >> 5;
    int lane = (int)(gt & 31);
    if (e >= E) return;
    long src, dst, typ;
    if (g_flag[0]) {
        const long long* p = (const long long*)ei;
        src = p[e]; dst = p[(long)E + e];
        typ = ((const long long*)et)[e];
    } else {
        const int* p = (const int*)ei;
        src = p[e]; dst = p[E + e];
        typ = ((const int*)et)[e];
    }
    if (do_count && lane == 0) atomicAdd(&g_inv[dst * 2 + typ], 1.0f);
    const float* X = dbuf(selX);
    float4 v = ((const float4*)(X + src * 128))[lane];
    float4* dp = (float4*)(g_sums + ((dst * 2 + typ) << 7)) + lane;
#if __CUDA_ARCH__ >= 900
    atomicAdd(dp, v);
#else
    atomicAdd(&dp->x, v.x); atomicAdd(&dp->y, v.y);
    atomicAdd(&dp->z, v.z); atomicAdd(&dp->w, v.w);
#endif
}

// ---------------- RGCN combine: mean0@W0 + mean1@W1 + x@Wroot + b ----------
__global__ void combine_kernel(int selX, int selC, const float* __restrict__ W_rel,
                               const float* __restrict__ W_root,
                               const float* __restrict__ b, int n) {
    extern __shared__ float sm[];
    float* sW = sm;
    float* sA = sm + 16384;
    int tid = threadIdx.x;
    int n0 = blockIdx.x * 64;
    int tx = tid & 31, ty = tid >> 5;
    const float* X = dbuf(selX);

    float acc[8][4];
    #pragma unroll
    for (int i = 0; i < 8; i++) { acc[i][0] = acc[i][1] = acc[i][2] = acc[i][3] = 0.f; }

    for (int p = 0; p < 3; p++) {
        __syncthreads();
        const float* W = (p < 2) ? (W_rel + p * 16384) : W_root;
        float4* sW4 = (float4*)sW;
        const float4* Wg = (const float4*)W;
        for (int i = tid; i < 4096; i += 256) sW4[i] = Wg[i];
        float4* sA4 = (float4*)sA;
        if (p < 2) {
            for (int i = tid; i < 2048; i += 256) {
                int r = i >> 5;
                int row = n0 + r;
                float4 v = make_float4(0.f, 0.f, 0.f, 0.f);
                if (row < n) {
                    float sc = g_inv[row * 2 + p];
                    const float4* sp = (const float4*)(g_sums + ((long)row * 2 + p) * 128);
                    v = sp[i & 31];
                    v.x *= sc; v.y *= sc; v.z *= sc; v.w *= sc;
                }
                sA4[i] = v;
            }
        } else {
            const float4* Xg = (const float4*)X;
            for (int i = tid; i < 2048; i += 256) {
                int r = i >> 5;
                int row = n0 + r;
                sA4[i] = (row < n) ? Xg[(long)row * 32 + (i & 31)] : make_float4(0.f, 0.f, 0.f, 0.f);
            }
        }
        __syncthreads();
        const float* a0 = sA + ty * 8 * 128;
        float4* sW4c = (float4*)sW;
        #pragma unroll 4
        for (int k = 0; k < 128; k++) {
            float4 w = sW4c[k * 32 + tx];
            #pragma unroll
            for (int i = 0; i < 8; i++) {
                float a = a0[i * 128 + k];
                acc[i][0] += a * w.x; acc[i][1] += a * w.y;
                acc[i][2] += a * w.z; acc[i][3] += a * w.w;
            }
        }
    }

    float4 bv = ((const float4*)b)[tx];
    float* C = dbuf(selC);
    #pragma unroll
    for (int i = 0; i < 8; i++) {
        int row = n0 + ty * 8 + i;
        if (row < n) {
            float4 o;
            o.x = acc[i][0] + bv.x; o.y = acc[i][1] + bv.y;
            o.z = acc[i][2] + bv.z; o.w = acc[i][3] + bv.w;
            ((float4*)C)[(long)row * 32 + tx] = o;
        }
    }
}

// ---------------- head: lrelu(x@Wo1+b1) @ Wo2 + b2 -> out[N,2] -------------
__global__ void head_kernel(int selX, const float* __restrict__ Wo1, const float* __restrict__ bo1,
                            const float* __restrict__ Wo2, const float* __restrict__ bo2,
                            float* __restrict__ out, int n) {
    extern __shared__ float sm[];
    float* sW = sm;                 // 128*128
    float* sA = sm + 16384;         // 64*128
    float* sW2 = sm + 16384 + 8192; // 128*2
    int tid = threadIdx.x;
    int n0 = blockIdx.x * 64;
    const float* X = dbuf(selX);

    float4* sW4 = (float4*)sW;
    const float4* Wg = (const float4*)Wo1;
    for (int i = tid; i < 4096; i += 256) sW4[i] = Wg[i];
    float4* sA4 = (float4*)sA;
    const float4* Xg = (const float4*)X;
    for (int i = tid; i < 2048; i += 256) {
        int r = i >> 5;
        int row = n0 + r;
        sA4[i] = (row < n) ? Xg[(long)row * 32 + (i & 31)] : make_float4(0.f, 0.f, 0.f, 0.f);
    }
    for (int i = tid; i < 256; i += 256) sW2[i] = Wo2[i];
    __syncthreads();

    int tx = tid & 31, ty = tid >> 5;
    float acc[8][4];
    #pragma unroll
    for (int i = 0; i < 8; i++) { acc[i][0] = acc[i][1] = acc[i][2] = acc[i][3] = 0.f; }
    const float* a0 = sA + ty * 8 * 128;
    #pragma unroll 4
    for (int k = 0; k < 128; k++) {
        float4 w = sW4[k * 32 + tx];
        #pragma unroll
        for (int i = 0; i < 8; i++) {
            float a = a0[i * 128 + k];
            acc[i][0] += a * w.x; acc[i][1] += a * w.y;
            acc[i][2] += a * w.z; acc[i][3] += a * w.w;
        }
    }

    float4 bv = ((const float4*)bo1)[tx];
    int c = tx * 4;
    float p0[8], p1[8];
    #pragma unroll
    for (int i = 0; i < 8; i++) {
        float t0 = lrelu(acc[i][0] + bv.x);
        float t1 = lrelu(acc[i][1] + bv.y);
        float t2 = lrelu(acc[i][2] + bv.z);
        float t3 = lrelu(acc[i][3] + bv.w);
        p0[i] = t0 * sW2[(c + 0) * 2] + t1 * sW2[(c + 1) * 2]
              + t2 * sW2[(c + 2) * 2] + t3 * sW2[(c + 3) * 2];
        p1[i] = t0 * sW2[(c + 0) * 2 + 1] + t1 * sW2[(c + 1) * 2 + 1]
              + t2 * sW2[(c + 2) * 2 + 1] + t3 * sW2[(c + 3) * 2 + 1];
    }
    #pragma unroll
    for (int off = 16; off > 0; off >>= 1) {
        #pragma unroll
        for (int i = 0; i < 8; i++) {
            p0[i] += __shfl_xor_sync(0xFFFFFFFFu, p0[i], off);
            p1[i] += __shfl_xor_sync(0xFFFFFFFFu, p1[i], off);
        }
    }
    if (tx == 0) {
        float b0 = bo2[0], b1 = bo2[1];
        #pragma unroll
        for (int i = 0; i < 8; i++) {
            int row = n0 + ty * 8 + i;
            if (row < n) {
                out[row * 2 + 0] = p0[i] + b0;
                out[row * 2 + 1] = p1[i] + b1;
            }
        }
    }
}

// ---------------- host ------------------------------------------------------
extern "C" void kernel_launch(void* const* d_in, const int* in_sizes, int n_in,
                              void* d_out, int out_size) {
    const float* des  = (const float*)d_in[0];
    const float* tw   = (const float*)d_in[1];
    const float* npr  = (const float*)d_in[2];
    const float* cpr  = (const float*)d_in[3];
    const void*  ei   = d_in[4];
    const void*  et   = d_in[5];
    const float* Wd   = (const float*)d_in[6];  const float* bd  = (const float*)d_in[7];
    const float* Wt   = (const float*)d_in[8];  const float* bt  = (const float*)d_in[9];
    const float* Wn   = (const float*)d_in[10]; const float* bn  = (const float*)d_in[11];
    const float* Wc   = (const float*)d_in[12]; const float* bc  = (const float*)d_in[13];
    const float* Win  = (const float*)d_in[14]; const float* bin = (const float*)d_in[15];
    const float* Wrel = (const float*)d_in[16];
    const float* Wroot= (const float*)d_in[17];
    const float* brg  = (const float*)d_in[18];
    const float* Wo1  = (const float*)d_in[19]; const float* bo1 = (const float*)d_in[20];
    const float* Wo2  = (const float*)d_in[21]; const float* bo2 = (const float*)d_in[22];
    float* out = (float*)d_out;

    int N = in_sizes[0] / 100;
    int E = in_sizes[5];

    const int SMEM_GEMM = (16384 + 8192) * 4;          // 96 KB
    const int SMEM_HEAD = (16384 + 8192 + 256) * 4;    // ~97 KB
    cudaFuncSetAttribute(gemm128_kernel, cudaFuncAttributeMaxDynamicSharedMemorySize, SMEM_GEMM);
    cudaFuncSetAttribute(combine_kernel, cudaFuncAttributeMaxDynamicSharedMemorySize, SMEM_GEMM);
    cudaFuncSetAttribute(head_kernel,    cudaFuncAttributeMaxDynamicSharedMemorySize, SMEM_HEAD);

    int nb = (N + 63) / 64;
    long n4 = (long)N * 64;                    // float4 count of g_sums
    int scatter_blocks = (int)(((long)E * 32 + 255) / 256);

    detect_kernel<<<1, 256>>>((const int*)ei);
    zero_kernel<<<4096, 256>>>(n4, 1, N * 2);
    fuse_kernel<<<nb, 256>>>(des, tw, npr, cpr, Wd, bd, Wt, bt, Wn, bn, Wc, bc, N);
    gemm128_kernel<<<nb, 256, SMEM_GEMM>>>(0, 1, Win, bin, N, 1);      // bufA -> bufB (x0)

    scatter_kernel<<<scatter_blocks, 256>>>(1, ei, et, E, 1);          // gather x0, scatter + count
    inv_kernel<<<(2 * N + 255) / 256, 256>>>(2 * N);
    combine_kernel<<<nb, 256, SMEM_GEMM>>>(1, 2, Wrel, Wroot, brg, N); // -> bufC (x1)

    zero_kernel<<<4096, 256>>>(n4, 0, 0);
    scatter_kernel<<<scatter_blocks, 256>>>(2, ei, et, E, 0);          // gather x1, scatter
    combine_kernel<<<nb, 256, SMEM_GEMM>>>(2, 0, Wrel, Wroot, brg, N); // -> bufA (x2)

    head_kernel<<<nb, 256, SMEM_HEAD>>>(0, Wo1, bo1, Wo2, bo2, out, N);
}